// round 10
// baseline (speedup 1.0000x reference)
#include <cuda_runtime.h>

// Problem constants (B=4, 96^3 vol, 4^3 patches, E=768)
#define TOKENS   13824
#define MASKN    10368
#define UNMASKN  3456
#define EDIM     768
#define KDIM     64
#define TT       64            // tokens per block (unmask: 16 spatial x 4 batches)
#define NTHREADS 768           // one thread per embed dim
#define NWARPS   24
#define UTILES   (UNMASKN / 16)   // 216 merged unmask blocks
#define MTILES   (MASKN / TT)     // 162 mask blocks
#define BATCH    4
#define PSROW    68            // padded ps row (floats), 16B-aligned
#define LOG2_1E4 13.287712379549449f

// positional-encoding table: g_pe[pos][c] = (c even ? sin : cos)(pos * 10000^-((c>>1)/128))
__device__ float g_pe[24][256];

__device__ __forceinline__ unsigned long long pack2(float a) {
    unsigned long long r;
    asm("mov.b64 %0, {%1, %1};" : "=l"(r) : "f"(a));
    return r;
}
__device__ __forceinline__ void fma2(unsigned long long& acc,
                                     unsigned long long a, unsigned long long b) {
    asm("fma.rn.f32x2 %0, %1, %2, %0;" : "+l"(acc) : "l"(a), "l"(b));
}
__device__ __forceinline__ void unpack2(unsigned long long v, float& lo, float& hi) {
    asm("mov.b64 {%0, %1}, %2;" : "=f"(lo), "=f"(hi) : "l"(v));
}

// Blocks [0,24): fill pe table row = blockIdx.x. Blocks [24,..): write mask_idx tail.
__global__ __launch_bounds__(256)
void init_pe_kernel(const int* __restrict__ perm, float* __restrict__ tail_out, int n_tail) {
    const int bi = blockIdx.x, tid = threadIdx.x;
    if (bi < 24) {
        const float invf = exp2f(-(float)(tid >> 1) * (LOG2_1E4 / 128.0f));
        float s, c;
        sincosf((float)bi * invf, &s, &c);
        g_pe[bi][tid] = (tid & 1) ? c : s;
    } else {
        const int i = (bi - 24) * 256 + tid;
        if (i < n_tail) tail_out[i] = (float)perm[i];
    }
}

// One block = 64 tokens x 768 dims, one thread per dim, 32 f32x2 token-pair accumulators.
// Per k: 1 LDG + 1 pack + 16 broadcast LDS.128 + 32 fma2  -> fma-pipe-bound.
// Blocks [0,216): unmask, 16 spatial tokens x ALL 4 batches (same perm -> shared W reads).
// Blocks [216,378): 64 mask tokens, computed once, written to all 4 batches.
__global__ __launch_bounds__(NTHREADS, 1)
void embed_kernel(const float* __restrict__ x,
                  const float* __restrict__ W,
                  const float* __restrict__ bias,
                  const float* __restrict__ mtok,
                  const float* __restrict__ gamma,
                  const float* __restrict__ beta,
                  const int*   __restrict__ perm,
                  float* __restrict__ out)
{
    __shared__ float ps[KDIM][PSROW];       // patch tile, k-major; token pairs contiguous
    __shared__ int   sH[TT], sW[TT], sD[TT];
    __shared__ float redS[TT][NWARPS + 1], redQ[TT][NWARPS + 1];
    __shared__ float meanv[TT], rstdv[TT];

    const int tid = threadIdx.x;
    const int bi  = blockIdx.x;
    const bool is_mask = bi >= UTILES;
    const int tile = is_mask ? bi - UTILES : bi;

    // ---- stage: 64 token rows (64 floats each) into SMEM, k-major ----
    for (int it = tid; it < TT * 16; it += NTHREADS) {
        const int tok = it & 63;      // consecutive lanes -> consecutive tokens (conflict-free STS)
        const int seg = it >> 6;      // 0..15 -> 4 k-values each
        float4 v;
        if (!is_mask) {
            const int j  = tok & 15;          // spatial token within tile
            const int bb = tok >> 4;          // batch
            const int s  = perm[MASKN + tile * 16 + j];
            const int h = s / 576, w = (s % 576) / 24, d = s % 24;
            if (seg == 0) { sH[tok] = h; sW[tok] = w; sD[tok] = d; }
            const int i = seg >> 2, jj = seg & 3;
            const size_t xi = (((size_t)(bb * 96 + 4 * h + i)) * 96 + (4 * w + jj)) * 96 + 4 * d;
            v = *(const float4*)(x + xi);
        } else {
            const int m = tile * TT + tok;
            const int s = perm[m];
            const int h = s / 576, w = (s % 576) / 24, d = s % 24;
            if (seg == 0) { sH[tok] = h; sW[tok] = w; sD[tok] = d; }
            v = *(const float4*)(mtok + (size_t)m * KDIM + seg * 4);
        }
        const int p = seg * 4;
        ps[p + 0][tok] = v.x; ps[p + 1][tok] = v.y;
        ps[p + 2][tok] = v.z; ps[p + 3][tok] = v.w;
    }
    __syncthreads();

    // ---- GEMM: thread owns dim `tid`; 32 f32x2 accumulators = 64 tokens ----
    unsigned long long acc[32];
    {
        const unsigned long long B0 = pack2(bias[tid]);
        #pragma unroll
        for (int t = 0; t < 32; t++) acc[t] = B0;
    }

    const float* wp = W + tid;
    #pragma unroll 2
    for (int k = 0; k < KDIM; k++) {
        const unsigned long long Wk = pack2(wp[(size_t)k * EDIM]);
        const ulonglong2* pp2 = (const ulonglong2*)ps[k];   // broadcast LDS.128 (4 tokens)
        #pragma unroll
        for (int q = 0; q < 16; q++) {
            const ulonglong2 pd = pp2[q];
            fma2(acc[2 * q],     pd.x, Wk);
            fma2(acc[2 * q + 1], pd.y, Wk);
        }
    }

    // ---- epilogue pass 1: + pe, LN stats (streaming over acc, no big v[] array) ----
    const int* sposArr = (tid < 256) ? sH : (tid < 512) ? sW : sD;
    const float* peb = &g_pe[0][tid & 255];      // row stride 256 floats
    const int warp = tid >> 5, lane = tid & 31;

    #pragma unroll
    for (int t2 = 0; t2 < 32; t2++) {
        float va, vb;
        unpack2(acc[t2], va, vb);
        va += __ldg(peb + sposArr[2 * t2] * 256);
        vb += __ldg(peb + sposArr[2 * t2 + 1] * 256);
        float s0 = va, q0 = va * va, s1 = vb, q1 = vb * vb;
        #pragma unroll
        for (int off = 16; off > 0; off >>= 1) {
            s0 += __shfl_xor_sync(0xffffffffu, s0, off);
            q0 += __shfl_xor_sync(0xffffffffu, q0, off);
            s1 += __shfl_xor_sync(0xffffffffu, s1, off);
            q1 += __shfl_xor_sync(0xffffffffu, q1, off);
        }
        if (lane == 0) {
            redS[2 * t2][warp] = s0;     redQ[2 * t2][warp] = q0;
            redS[2 * t2 + 1][warp] = s1; redQ[2 * t2 + 1][warp] = q1;
        }
    }
    __syncthreads();

    if (tid < TT) {
        float sm = 0.f, sq = 0.f;
        #pragma unroll
        for (int wi = 0; wi < NWARPS; wi++) { sm += redS[tid][wi]; sq += redQ[tid][wi]; }
        const float mn = sm * (1.0f / (float)EDIM);
        const float vr = sq * (1.0f / (float)EDIM) - mn * mn;
        meanv[tid] = mn;
        rstdv[tid] = rsqrtf(vr + 0.001f);
    }
    __syncthreads();

    // ---- epilogue pass 2: normalize + store ----
    const float gm = gamma[tid];
    const float bt = beta[tid];

    if (!is_mask) {
        float* base = out + (size_t)(tile * 16) * EDIM + tid;
        const size_t bstride = (size_t)TOKENS * EDIM;
        #pragma unroll
        for (int t2 = 0; t2 < 32; t2++) {
            const int ta = 2 * t2, tb = ta + 1;
            float va, vb;
            unpack2(acc[t2], va, vb);
            va += __ldg(peb + sposArr[ta] * 256);
            vb += __ldg(peb + sposArr[tb] * 256);
            va = (va - meanv[ta]) * rstdv[ta] * gm + bt;
            vb = (vb - meanv[tb]) * rstdv[tb] * gm + bt;
            base[(size_t)(ta >> 4) * bstride + (size_t)(ta & 15) * EDIM] = va;
            base[(size_t)(tb >> 4) * bstride + (size_t)(tb & 15) * EDIM] = vb;
        }
    } else {
        float* base = out + (size_t)(UNMASKN + tile * TT) * EDIM + tid;
        const size_t bstride = (size_t)TOKENS * EDIM;
        #pragma unroll
        for (int t2 = 0; t2 < 32; t2++) {
            const int ta = 2 * t2, tb = ta + 1;
            float va, vb;
            unpack2(acc[t2], va, vb);
            va += __ldg(peb + sposArr[ta] * 256);
            vb += __ldg(peb + sposArr[tb] * 256);
            va = (va - meanv[ta]) * rstdv[ta] * gm + bt;
            vb = (vb - meanv[tb]) * rstdv[tb] * gm + bt;
            float* pa = base + (size_t)ta * EDIM;
            float* pb = base + (size_t)tb * EDIM;
            #pragma unroll
            for (int bb = 0; bb < BATCH; bb++) {
                pa[bb * bstride] = va;
                pb[bb * bstride] = vb;
            }
        }
    }
}

extern "C" void kernel_launch(void* const* d_in, const int* in_sizes, int n_in,
                              void* d_out, int out_size) {
    const float* x     = (const float*)d_in[0];
    const float* W     = (const float*)d_in[1];
    const float* bias  = (const float*)d_in[2];
    const float* mtok  = (const float*)d_in[3];
    const float* gamma = (const float*)d_in[4];
    const float* beta  = (const float*)d_in[5];
    const int*   perm  = (const int*)d_in[6];
    float* out = (float*)d_out;

    const long long main_elems = (long long)BATCH * TOKENS * EDIM;  // 42,467,328
    const long long extra = (long long)out_size - main_elems;       // expected 10368 (mask_idx)
    const int n_tail = extra > 0 ? (int)extra : 0;
    const int tail_blocks = (n_tail + 255) / 256;

    // init: pe table (24 blocks) + mask_idx tail writes
    init_pe_kernel<<<24 + tail_blocks, 256>>>(perm, out + main_elems, n_tail);

    embed_kernel<<<UTILES + MTILES, NTHREADS>>>(x, W, bias, mtok, gamma, beta, perm, out);
}

// round 11
// speedup vs baseline: 2.5491x; 2.5491x over previous
#include <cuda_runtime.h>

// Problem constants (B=4, 96^3 vol, 4^3 patches, E=768)
#define TOKENS   13824
#define MASKN    10368
#define UNMASKN  3456
#define EDIM     768
#define KDIM     64
#define TT       16            // tokens per block
#define NTHREADS 384           // 2 dims per thread: tid, tid+384
#define NWARPS   12
#define UTILES   (UNMASKN / TT)   // 216
#define MTILES   (MASKN / TT)     // 648
#define BATCH    4
#define LOG2_1E4 13.287712379549449f

// positional-encoding table: g_pe[pos][c] = (c even ? sin : cos)(pos * 10000^-((c>>1)/128))
__device__ float g_pe[24][256];

__device__ __forceinline__ unsigned long long pack2(float a) {
    unsigned long long r;
    asm("mov.b64 %0, {%1, %1};" : "=l"(r) : "f"(a));
    return r;
}
__device__ __forceinline__ void fma2(unsigned long long& acc,
                                     unsigned long long a, unsigned long long b) {
    asm("fma.rn.f32x2 %0, %1, %2, %0;" : "+l"(acc) : "l"(a), "l"(b));
}
__device__ __forceinline__ void unpack2(unsigned long long v, float& lo, float& hi) {
    asm("mov.b64 {%0, %1}, %2;" : "=f"(lo), "=f"(hi) : "l"(v));
}

// Blocks [0,24): fill pe table row = blockIdx.x. Blocks [24,..): write mask_idx tail.
__global__ __launch_bounds__(256)
void init_pe_kernel(const int* __restrict__ perm, float* __restrict__ tail_out, int n_tail) {
    const int bi = blockIdx.x, tid = threadIdx.x;
    if (bi < 24) {
        const float invf = exp2f(-(float)(tid >> 1) * (LOG2_1E4 / 128.0f));
        float s, c;
        sincosf((float)bi * invf, &s, &c);
        g_pe[bi][tid] = (tid & 1) ? c : s;
    } else {
        const int i = (bi - 24) * 256 + tid;
        if (i < n_tail) tail_out[i] = (float)perm[i];
    }
}

// One block = 16 tokens x 768 dims; thread owns dims {tid, tid+384}.
// 384 thr, <=56 regs -> 3 blocks/SM = 36 warps: max latency hiding at spill-safe regs.
// Blocks [0, 864): unmask (per batch). Blocks [864, 1512): mask tokens,
// computed once and written to all 4 batches (batch-invariant incl. LN).
__global__ __launch_bounds__(NTHREADS, 3)
void embed_kernel(const float* __restrict__ x,
                  const float* __restrict__ W,
                  const float* __restrict__ bias,
                  const float* __restrict__ mtok,
                  const float* __restrict__ gamma,
                  const float* __restrict__ beta,
                  const int*   __restrict__ perm,
                  float* __restrict__ out)
{
    __shared__ float ps[KDIM][TT];          // patch tile, k-major; token pairs contiguous
    __shared__ int   sH[TT], sW[TT], sD[TT];
    __shared__ float redS[TT][NWARPS + 1], redQ[TT][NWARPS + 1];
    __shared__ float meanv[TT], rstdv[TT];

    const int tid = threadIdx.x;
    const int bi  = blockIdx.x;
    const bool is_mask = bi >= BATCH * UTILES;
    int b = 0, tile;
    if (!is_mask) { b = bi / UTILES; tile = bi % UTILES; }
    else          { tile = bi - BATCH * UTILES; }

    // ---- stage: gather 16 patch rows (64 floats each) into SMEM (threads 0-255) ----
    if (tid < 256) {
        const int tok = tid & 15;     // consecutive lanes -> consecutive tokens (conflict-free STS)
        const int seg = tid >> 4;     // 0..15 -> 4 floats each
        const int m   = tile * TT + tok;
        const int s   = is_mask ? perm[m] : perm[MASKN + m];
        const int h = s / 576, w = (s % 576) / 24, d = s % 24;
        if (seg == 0) { sH[tok] = h; sW[tok] = w; sD[tok] = d; }
        float4 v;
        if (!is_mask) {
            const int i = seg >> 2, j = seg & 3;
            const size_t xi = (((size_t)(b * 96 + 4 * h + i)) * 96 + (4 * w + j)) * 96 + 4 * d;
            v = *(const float4*)(x + xi);
        } else {
            v = *(const float4*)(mtok + (size_t)m * KDIM + seg * 4);
        }
        const int p = seg * 4;
        ps[p + 0][tok] = v.x; ps[p + 1][tok] = v.y;
        ps[p + 2][tok] = v.z; ps[p + 3][tok] = v.w;
    }
    __syncthreads();

    // ---- GEMM: thread owns dims {tid, tid+384}; 16 f32x2 token-pair accumulators ----
    unsigned long long a0[8], a1[8];
    {
        const unsigned long long B0 = pack2(bias[tid]);
        const unsigned long long B1 = pack2(bias[tid + 384]);
        #pragma unroll
        for (int t = 0; t < 8; t++) { a0[t] = B0; a1[t] = B1; }
    }

    const float* wp = W + tid;
    #pragma unroll 4
    for (int k = 0; k < KDIM; k++) {
        const unsigned long long W0 = pack2(wp[k * EDIM]);
        const unsigned long long W1 = pack2(wp[k * EDIM + 384]);
        const ulonglong2* pp2 = (const ulonglong2*)ps[k];   // LDS.128 broadcast (4 tokens)
        #pragma unroll
        for (int q = 0; q < 4; q++) {
            const ulonglong2 pd = pp2[q];
            fma2(a0[2 * q],     pd.x, W0);
            fma2(a1[2 * q],     pd.x, W1);
            fma2(a0[2 * q + 1], pd.y, W0);
            fma2(a1[2 * q + 1], pd.y, W1);
        }
    }

    // ---- epilogue: unpack, + positional encoding from table ----
    float v0[TT], v1[TT];
    #pragma unroll
    for (int t = 0; t < 8; t++) {
        unpack2(a0[t], v0[2 * t], v0[2 * t + 1]);
        unpack2(a1[t], v1[2 * t], v1[2 * t + 1]);
    }

    // dim e0 = tid: H if tid<256 else W.  dim e1 = tid+384: W if tid<128 else D.
    const int* spos0 = (tid < 256) ? sH : sW;
    const int* spos1 = (tid < 128) ? sW : sD;
    const int pecol0 = tid & 255;
    const int pecol1 = (tid + 128) & 255;
    const int warp = tid >> 5, lane = tid & 31;

    #pragma unroll
    for (int t = 0; t < TT; t++) {
        v0[t] += __ldg(&g_pe[spos0[t]][pecol0]);
        v1[t] += __ldg(&g_pe[spos1[t]][pecol1]);

        float sm = v0[t] + v1[t];
        float sq = v0[t] * v0[t] + v1[t] * v1[t];
        #pragma unroll
        for (int off = 16; off > 0; off >>= 1) {
            sm += __shfl_xor_sync(0xffffffffu, sm, off);
            sq += __shfl_xor_sync(0xffffffffu, sq, off);
        }
        if (lane == 0) { redS[t][warp] = sm; redQ[t][warp] = sq; }
    }
    __syncthreads();

    if (tid < TT) {
        float sm = 0.f, sq = 0.f;
        #pragma unroll
        for (int wi = 0; wi < NWARPS; wi++) { sm += redS[tid][wi]; sq += redQ[tid][wi]; }
        const float mn = sm * (1.0f / (float)EDIM);
        const float vr = sq * (1.0f / (float)EDIM) - mn * mn;
        meanv[tid] = mn;
        rstdv[tid] = rsqrtf(vr + 0.001f);
    }
    __syncthreads();

    const float g0  = gamma[tid], g1  = gamma[tid + 384];
    const float be0 = beta[tid],  be1 = beta[tid + 384];

    if (!is_mask) {
        float* o = out + ((size_t)b * TOKENS + (size_t)tile * TT) * EDIM + tid;
        #pragma unroll
        for (int t = 0; t < TT; t++) {
            const float mn = meanv[t], rs = rstdv[t];
            o[(size_t)t * EDIM]       = (v0[t] - mn) * rs * g0 + be0;
            o[(size_t)t * EDIM + 384] = (v1[t] - mn) * rs * g1 + be1;
        }
    } else {
        float* o = out + ((size_t)UNMASKN + (size_t)tile * TT) * EDIM + tid;
        const size_t bstride = (size_t)TOKENS * EDIM;
        #pragma unroll
        for (int t = 0; t < TT; t++) {
            const float mn = meanv[t], rs = rstdv[t];
            const float r0 = (v0[t] - mn) * rs * g0 + be0;
            const float r1 = (v1[t] - mn) * rs * g1 + be1;
            #pragma unroll
            for (int bb = 0; bb < BATCH; bb++) {
                float* op = o + bb * bstride + (size_t)t * EDIM;
                op[0]   = r0;
                op[384] = r1;
            }
        }
    }
}

extern "C" void kernel_launch(void* const* d_in, const int* in_sizes, int n_in,
                              void* d_out, int out_size) {
    const float* x     = (const float*)d_in[0];
    const float* W     = (const float*)d_in[1];
    const float* bias  = (const float*)d_in[2];
    const float* mtok  = (const float*)d_in[3];
    const float* gamma = (const float*)d_in[4];
    const float* beta  = (const float*)d_in[5];
    const int*   perm  = (const int*)d_in[6];
    float* out = (float*)d_out;

    const long long main_elems = (long long)BATCH * TOKENS * EDIM;  // 42,467,328
    const long long extra = (long long)out_size - main_elems;       // expected 10368 (mask_idx)
    const int n_tail = extra > 0 ? (int)extra : 0;
    const int tail_blocks = (n_tail + 255) / 256;

    // init: pe table (24 blocks) + mask_idx tail writes
    init_pe_kernel<<<24 + tail_blocks, 256>>>(perm, out + main_elems, n_tail);

    embed_kernel<<<BATCH * UTILES + MTILES, NTHREADS>>>(x, W, bias, mtok, gamma, beta, perm, out);
}